// round 14
// baseline (speedup 1.0000x reference)
#include <cuda_runtime.h>
#include <math_constants.h>

// Problem dims
#define BATCH 64
#define DIM   768
#define MEM   2048
#define NCLS  1000

#define EC  48                 // e-chunk per score block (DIM/EC = 16)
#define NEC (DIM / EC)
#define KC  16                 // gemm k-chunk
#define NKCH (DIM / KC)        // 48 k-chunks
#define NJT  6                 // j-tiles of 128

// Scratch (allocation-free). Invariant: all three buffers are ZERO at the
// start of every launch — established by static zero-init on module load,
// maintained by each buffer's last reader re-zeroing it (self-cleaning).
__device__ float g_q[BATCH * DIM];
__device__ float g_t[BATCH * DIM];
__device__ float g_scores[BATCH * MEM];
// Monotonic reader counters (never reset; per-replay arrival counts are exact
// multiples, so mod-N identifies the last reader of THIS replay).
__device__ unsigned g_qcnt[NKCH];          // 6 readers per chunk per replay
__device__ unsigned g_tcnt[BATCH * NEC];   // 2 readers per slice per replay

// ---------------------------------------------------------------------------
// GEMM stage: C[64,768] += A[64,768] @ W[768,768]  (row-major, split-K)
// grid = (6 j-tiles of 128, 48 k-chunks of 16), block = 256 threads.
// Thread: 4 consecutive j (float4 W load) x 8 b (smem broadcast), 8x W reuse.
// stage 0: A = x, C = g_q (plain first node).
// stage 1: A = g_q (PDL sync first), C = g_t; the 6th reader of each g_q
//          chunk zeroes it for the next replay (all 6 have copied to smem).
// ---------------------------------------------------------------------------
__global__ void __launch_bounds__(256) gemm_stage(const float* __restrict__ Aext,
                                                  const float* __restrict__ W,
                                                  int stage) {
    if (stage != 0) cudaGridDependencySynchronize();  // g_q complete

    const float* A = (stage == 0) ? Aext : g_q;
    float* Cc      = (stage == 0) ? g_q  : g_t;

    __shared__ float xs[KC][BATCH + 1];
    __shared__ int   sh_clean;

    const int k0 = blockIdx.y * KC;

    for (int i = threadIdx.x; i < BATCH * KC; i += 256) {
        int b = i >> 4;          // i / 16
        int d = i & (KC - 1);    // i % 16
        xs[d][b] = A[b * DIM + k0 + d];
    }
    __syncthreads();             // all loads of this block's A chunk complete

    if (stage != 0) {
        if (threadIdx.x == 0) {
            const unsigned old = atomicAdd(&g_qcnt[blockIdx.y], 1u);
            sh_clean = ((old % 6u) == 5u) ? 1 : 0;   // last of 6 readers
        }
        __syncthreads();
        if (sh_clean) {          // zero this g_q chunk for the next replay
            for (int i = threadIdx.x; i < BATCH * KC; i += 256) {
                int b = i >> 4;
                int d = i & (KC - 1);
                g_q[b * DIM + k0 + d] = 0.0f;
            }
        }
    }

    const int jv = threadIdx.x & 31;
    const int bg = threadIdx.x >> 5;
    const int j  = blockIdx.x * 128 + jv * 4;

    float acc[8][4];
    #pragma unroll
    for (int bb = 0; bb < 8; bb++)
        #pragma unroll
        for (int jj = 0; jj < 4; jj++) acc[bb][jj] = 0.0f;

    #pragma unroll
    for (int d = 0; d < KC; d++) {
        const float4 w = *(const float4*)&W[(size_t)(k0 + d) * DIM + j];
        #pragma unroll
        for (int bb = 0; bb < 8; bb++) {
            const float xv = xs[d][bg * 8 + bb];
            acc[bb][0] = fmaf(xv, w.x, acc[bb][0]);
            acc[bb][1] = fmaf(xv, w.y, acc[bb][1]);
            acc[bb][2] = fmaf(xv, w.z, acc[bb][2]);
            acc[bb][3] = fmaf(xv, w.w, acc[bb][3]);
        }
    }

    #pragma unroll
    for (int bb = 0; bb < 8; bb++) {
        const int b = bg * 8 + bb;
        atomicAdd(&Cc[b * DIM + j + 0], acc[bb][0]);
        atomicAdd(&Cc[b * DIM + j + 1], acc[bb][1]);
        atomicAdd(&Cc[b * DIM + j + 2], acc[bb][2]);
        atomicAdd(&Cc[b * DIM + j + 3], acc[bb][3]);
    }
    cudaTriggerProgrammaticLaunchCompletion();
}

// ---------------------------------------------------------------------------
// Dominant kernel (proven config, unroll 8): scores[b,m] += sum_e t[b,e]*mem.
// Streams 402 MB once. grid = (2, 16, 64) = 2048 blocks x 256 threads.
// The 2nd reader of each g_t slice zeroes it (both have copied to smem).
// ---------------------------------------------------------------------------
__global__ void __launch_bounds__(256) score_partial(const float* __restrict__ mem) {
    const int b  = blockIdx.z;
    const int ey = blockIdx.y;
    const int e0 = ey * EC;
    const int m  = blockIdx.x * 1024 + threadIdx.x * 4;
    const float4* mp = (const float4*)(mem + (size_t)b * DIM * MEM
                                           + (size_t)e0 * MEM + m);

    cudaGridDependencySynchronize();   // g_t complete

    __shared__ float ts[EC];
    __shared__ int   sh_clean;
    if (threadIdx.x < EC) ts[threadIdx.x] = g_t[b * DIM + e0 + threadIdx.x];
    __syncthreads();                   // slice fully copied to smem

    if (threadIdx.x == 0) {
        const unsigned old = atomicAdd(&g_tcnt[b * NEC + ey], 1u);
        sh_clean = ((old & 1u) == 1u) ? 1 : 0;   // 2nd of 2 readers
    }
    __syncthreads();
    if (sh_clean && threadIdx.x < EC)  // zero slice for next replay
        g_t[b * DIM + e0 + threadIdx.x] = 0.0f;

    float ax = 0.f, ay = 0.f, az = 0.f, aw = 0.f;
    #pragma unroll 8
    for (int e = 0; e < EC; e++) {
        const float4 v = __ldcs(&mp[(size_t)e * (MEM / 4)]);
        const float w = ts[e];  // warp-uniform broadcast
        ax = fmaf(w, v.x, ax);
        ay = fmaf(w, v.y, ay);
        az = fmaf(w, v.z, az);
        aw = fmaf(w, v.w, aw);
    }

    float* sp = &g_scores[b * MEM + m];
    atomicAdd(sp + 0, ax);
    atomicAdd(sp + 1, ay);
    atomicAdd(sp + 2, az);
    atomicAdd(sp + 3, aw);
    cudaTriggerProgrammaticLaunchCompletion();
}

// ---------------------------------------------------------------------------
// Fused epilogue: leaky-relu(scores) scattered into shared logits[1000]
// (smem atomics), softmax, write out. Sole reader of g_scores -> re-zeroes
// each element right after reading (maintains the launch-entry invariant).
// 64 blocks x 512 threads. PDL: logits zero + label-dtype detect pre-sync.
// Label dtype: int64 labels in [0,1000) have all-zero odd 32-bit words.
// ---------------------------------------------------------------------------
__global__ void __launch_bounds__(512) epilogue(const int* __restrict__ lab32,
                                                float* __restrict__ out) {
    const int b = blockIdx.x;
    const int tid = threadIdx.x;

    __shared__ float logits[NCLS];
    __shared__ float red[16];
    __shared__ int   sh_is64;

    for (int i = tid; i < NCLS; i += 512) logits[i] = 0.0f;
    if (tid == 0) {
        int any = 0;
        #pragma unroll
        for (int k = 0; k < 32; k++) any |= lab32[2 * k + 1];
        sh_is64 = (any == 0) ? 1 : 0;
    }
    __syncthreads();
    const int is64 = sh_is64;

    cudaGridDependencySynchronize();   // g_scores complete

    for (int i = tid; i < MEM; i += 512) {
        const size_t idx = (size_t)b * MEM + i;
        const float s = g_scores[idx];
        g_scores[idx] = 0.0f;          // self-clean for next replay
        const float sv = (s >= 0.0f) ? s : 0.01f * s;
        int lab = is64 ? lab32[2 * idx] : lab32[idx];
        lab = min(max(lab, 0), NCLS - 1);
        atomicAdd(&logits[lab], sv);
    }
    __syncthreads();

    // --- max ---
    float mx = -CUDART_INF_F;
    for (int i = tid; i < NCLS; i += 512) mx = fmaxf(mx, logits[i]);
    #pragma unroll
    for (int o = 16; o > 0; o >>= 1) mx = fmaxf(mx, __shfl_xor_sync(0xffffffffu, mx, o));
    if ((tid & 31) == 0) red[tid >> 5] = mx;
    __syncthreads();
    if (tid < 32) {
        float v = (tid < 16) ? red[tid] : -CUDART_INF_F;
        #pragma unroll
        for (int o = 8; o > 0; o >>= 1) v = fmaxf(v, __shfl_xor_sync(0xffffffffu, v, o));
        if (tid == 0) red[0] = v;
    }
    __syncthreads();
    mx = red[0];
    __syncthreads();

    // --- exp + sum ---
    float sum = 0.0f;
    for (int i = tid; i < NCLS; i += 512) {
        const float e = __expf(logits[i] - mx);
        logits[i] = e;
        sum += e;
    }
    #pragma unroll
    for (int o = 16; o > 0; o >>= 1) sum += __shfl_xor_sync(0xffffffffu, sum, o);
    if ((tid & 31) == 0) red[tid >> 5] = sum;
    __syncthreads();
    if (tid < 32) {
        float v = (tid < 16) ? red[tid] : 0.0f;
        #pragma unroll
        for (int o = 8; o > 0; o >>= 1) v += __shfl_xor_sync(0xffffffffu, v, o);
        if (tid == 0) red[0] = v;
    }
    __syncthreads();
    const float inv = 1.0f / red[0];

    for (int i = tid; i < NCLS; i += 512) out[b * NCLS + i] = logits[i] * inv;
}

// ---------------------------------------------------------------------------
// Launch (4 nodes): gemm1 -> gemm2 (PDL) -> score (PDL) -> epilogue (PDL).
// No zero kernel: scratch zeroed by module init + self-cleaning readers.
// Inputs mapped by element count: x 49152, mem 100663296, labels 131072,
// W_Q / W_K 589824 each (W_Q first).  Output: f32[64,1000].
// ---------------------------------------------------------------------------
template <typename... Args>
static inline void launch_pdl(void (*kern)(Args...), dim3 grid, dim3 block,
                              Args... args) {
    cudaLaunchConfig_t cfg = {};
    cfg.gridDim = grid;
    cfg.blockDim = block;
    cfg.dynamicSmemBytes = 0;
    cfg.stream = 0;
    cudaLaunchAttribute attr[1];
    attr[0].id = cudaLaunchAttributeProgrammaticStreamSerialization;
    attr[0].val.programmaticStreamSerializationAllowed = 1;
    cfg.attrs = attr;
    cfg.numAttrs = 1;
    cudaLaunchKernelEx(&cfg, kern, args...);
}

extern "C" void kernel_launch(void* const* d_in, const int* in_sizes, int n_in,
                              void* d_out, int out_size) {
    const float* x   = nullptr;
    const float* mem = nullptr;
    const int* labs  = nullptr;
    const float* W_Q = nullptr;
    const float* W_K = nullptr;

    for (int i = 0; i < n_in; i++) {
        const int sz = in_sizes[i];
        if (sz == BATCH * DIM)            x    = (const float*)d_in[i];
        else if (sz == BATCH * DIM * MEM) mem  = (const float*)d_in[i];
        else if (sz == BATCH * MEM)       labs = (const int*)d_in[i];
        else if (sz == DIM * DIM) {
            if (!W_Q) W_Q = (const float*)d_in[i];
            else      W_K = (const float*)d_in[i];
        }
    }
    float* out = (float*)d_out;

    gemm_stage<<<dim3(NJT, NKCH), 256>>>(x, W_K, 0);             // q = x @ W_K
    launch_pdl(gemm_stage, dim3(NJT, NKCH), dim3(256), x, W_Q, 1);  // t = q @ W_Q
    launch_pdl(score_partial, dim3(2, NEC, BATCH), dim3(256), mem);
    launch_pdl(epilogue, dim3(BATCH), dim3(512), labs, out);
}